// round 10
// baseline (speedup 1.0000x reference)
#include <cuda_runtime.h>
#include <math.h>

// ---------------- problem constants ----------------
#define B_  4
#define C_  512
#define H_  128
#define W_  128
#define HW_ 16384          // H*W
#define CQ_ 128            // C/4
#define CE_ 64             // C/8
#define P_  65536          // B*H*W

// ---------------- device scratch (no allocs allowed) ----------------
__device__ float g_E[4L * B_ * C_ * HW_];     // 4 edge maps, [k][b][c][hw]
__device__ float g_ef[(long)B_ * C_ * HW_];   // branch features, [b][c][hw]
__device__ float g_z [(long)B_ * C_ * HW_];   // fusion conv out,  [b][c][hw]
__device__ float g_wbT[4 * C_ * CQ_];         // w_branch transposed [k][c][o]
__device__ float g_wfT[C_ * C_];              // w_fuse   transposed [c][o]
__device__ float g_wfS[B_ * C_ * C_];         // att-scaled fuse weights [b][c][o]
__device__ float g_pooled[B_ * C_];           // atomic-accumulated pool sums
__device__ float g_att   [B_ * C_];

__device__ __forceinline__ float gelu_exact(float v) {
    return 0.5f * v * (1.0f + erff(v * 0.70710678118654752440f));
}

__device__ __forceinline__ unsigned f2tf(float f) {
    unsigned u;
    asm("cvt.rna.tf32.f32 %0, %1;" : "=r"(u) : "f"(f));
    return u;
}

__device__ __forceinline__ void mma8(float c[4],
                                     unsigned a0, unsigned a1, unsigned a2, unsigned a3,
                                     unsigned b0, unsigned b1) {
    asm volatile(
        "mma.sync.aligned.m16n8k8.row.col.f32.tf32.tf32.f32 "
        "{%0,%1,%2,%3}, {%4,%5,%6,%7}, {%8,%9}, {%0,%1,%2,%3};\n"
        : "+f"(c[0]), "+f"(c[1]), "+f"(c[2]), "+f"(c[3])
        : "r"(a0), "r"(a1), "r"(a2), "r"(a3), "r"(b0), "r"(b1));
}

__device__ __forceinline__ void cp16(void* smem, const void* gmem) {
    unsigned s = (unsigned)__cvta_generic_to_shared(smem);
    asm volatile("cp.async.cg.shared.global [%0], [%1], 16;\n" :: "r"(s), "l"(gmem));
}
#define CP_COMMIT asm volatile("cp.async.commit_group;\n" ::: "memory")
#define CP_WAIT2  asm volatile("cp.async.wait_group 2;\n" ::: "memory")
#define CP_WAIT1  asm volatile("cp.async.wait_group 1;\n" ::: "memory")
#define CP_WAIT0  asm volatile("cp.async.wait_group 0;\n" ::: "memory")

// ---------------- K0: weight transposes + zero pooled ----------------
__global__ void k_transpose(const float* __restrict__ wb, const float* __restrict__ wf) {
    int i = blockIdx.x * 256 + threadIdx.x;
    if (i < 4 * C_ * CQ_) {              // wbT[(k*C + c)*CQ + o] = wb[(k*CQ+o)*C + c]
        int o = i & (CQ_ - 1);
        int c = (i >> 7) & (C_ - 1);
        int k = i >> 16;
        g_wbT[i] = wb[(k * CQ_ + o) * C_ + c];
    }
    if (i < C_ * C_) {                   // wfT[c*C + o] = wf[o*C + c]
        int o = i & (C_ - 1);
        int c = i >> 9;
        g_wfT[i] = wf[o * C_ + c];
    }
    if (i < B_ * C_) g_pooled[i] = 0.f;  // reset pool accumulators every launch
}

// ---------------- K1: fixed 3x3 stencils -> 4 edge maps ----------------
__global__ void k_edge(const float* __restrict__ x) {
    int bc = blockIdx.x;                                  // b*C + c
    const float* xp = x + (long)bc * HW_;
    float* e0 = g_E + (long)(0 * B_ * C_ + bc) * HW_;
    float* e1 = g_E + (long)(1 * B_ * C_ + bc) * HW_;
    float* e2 = g_E + (long)(2 * B_ * C_ + bc) * HW_;
    float* e3 = g_E + (long)(3 * B_ * C_ + bc) * HW_;

    for (int p = threadIdx.x; p < HW_; p += blockDim.x) {
        int h = p >> 7, w = p & (W_ - 1);
        int hm = h - 1, hp = h + 1, wm = w - 1, wp = w + 1;
        bool ht = hm >= 0, hb = hp < H_, wl = wm >= 0, wr = wp < W_;
        float v00 = (ht && wl) ? xp[hm * W_ + wm] : 0.f;
        float v01 = (ht)       ? xp[hm * W_ + w ] : 0.f;
        float v02 = (ht && wr) ? xp[hm * W_ + wp] : 0.f;
        float v10 = (wl)       ? xp[h  * W_ + wm] : 0.f;
        float v11 =              xp[h  * W_ + w ];
        float v12 = (wr)       ? xp[h  * W_ + wp] : 0.f;
        float v20 = (hb && wl) ? xp[hp * W_ + wm] : 0.f;
        float v21 = (hb)       ? xp[hp * W_ + w ] : 0.f;
        float v22 = (hb && wr) ? xp[hp * W_ + wp] : 0.f;

        float sh  = (v02 - v00) + 2.f * (v12 - v10) + (v22 - v20);
        float sv  = (v20 - v00) + 2.f * (v21 - v01) + (v22 - v02);
        float lap = v01 + v10 + v12 + v21 - 4.f * v11;
        float d1  = v00 - v02 - v20 + v22;          // K_D2 = -K_D1 => diag = |d1|

        float sobel = sqrtf(sh * sh + sv * sv + 1e-8f);
        float lapA  = fabsf(lap);
        float diag  = fabsf(d1);
        float grad  = sqrtf(sobel * sobel + lapA * lapA + 1e-8f);

        e0[p] = sobel; e1[p] = lapA; e2[p] = diag; e3[p] = grad;
    }
}

// ============== shared TF32 MMA tile core (cp.async 3-stage pipelined) ==============
// Block tile 128(M) x 128(N), K-tile 16, 256 threads = 8 warps (2 m x 4 n),
// warp tile 64x32 = 4x4 m16n8k8 atoms. A and B are K-major f32 in gmem.
// Raw f32 staged via cp.async; cvt.rna.tf32 on the fragment-load side.
#define SPAD 132
#define NKT  (C_ / 16)     // 32 k-tiles
#define TILE_F (16 * SPAD) // floats per stage buffer

__device__ __forceinline__ void issue_tile(
    const float* __restrict__ Ag, long ldA, int mBase,
    const float* __restrict__ Bg, int ldB, int nBase,
    int kc, float* As, float* Bs, int tid)
{
    #pragma unroll
    for (int i = 0; i < 2; i++) {
        int idx = tid + i * 256;          // 0..511
        int row = idx >> 5;               // 0..15
        int c4  = (idx & 31) * 4;         // 0..124
        cp16(&As[row * SPAD + c4], &Ag[(long)(kc + row) * ldA + mBase + c4]);
        cp16(&Bs[row * SPAD + c4], &Bg[(long)(kc + row) * ldB + nBase + c4]);
    }
}

__device__ __forceinline__ void mma_kloop_pipe(
    const float* __restrict__ Ag, long ldA, int mBase,
    const float* __restrict__ Bg, int ldB, int nBase,
    float* AsBuf, float* BsBuf,           // each 3 * TILE_F floats
    float acc[4][4][4])
{
    int tid = threadIdx.x;
    int lane = tid & 31, w = tid >> 5;
    int wm = (w >> 2) * 64, wn = (w & 3) * 32;
    int grp = lane >> 2, thr = lane & 3;

    #pragma unroll
    for (int mi = 0; mi < 4; mi++)
        #pragma unroll
        for (int nj = 0; nj < 4; nj++)
            #pragma unroll
            for (int r = 0; r < 4; r++) acc[mi][nj][r] = 0.f;

    issue_tile(Ag, ldA, mBase, Bg, ldB, nBase, 0,  AsBuf,              BsBuf,              tid); CP_COMMIT;
    issue_tile(Ag, ldA, mBase, Bg, ldB, nBase, 16, AsBuf + TILE_F,     BsBuf + TILE_F,     tid); CP_COMMIT;
    issue_tile(Ag, ldA, mBase, Bg, ldB, nBase, 32, AsBuf + 2 * TILE_F, BsBuf + 2 * TILE_F, tid); CP_COMMIT;

    int buf = 0;
    for (int kt = 0; kt < NKT; kt++) {
        if (kt < NKT - 2)       { CP_WAIT2; }
        else if (kt == NKT - 2) { CP_WAIT1; }
        else                    { CP_WAIT0; }
        __syncthreads();

        float* As = AsBuf + buf * TILE_F;
        float* Bs = BsBuf + buf * TILE_F;

        #pragma unroll
        for (int kk = 0; kk < 16; kk += 8) {
            unsigned bf[4][2];
            #pragma unroll
            for (int nj = 0; nj < 4; nj++) {
                bf[nj][0] = f2tf(Bs[(kk + thr)     * SPAD + wn + nj * 8 + grp]);
                bf[nj][1] = f2tf(Bs[(kk + 4 + thr) * SPAD + wn + nj * 8 + grp]);
            }
            #pragma unroll
            for (int mi = 0; mi < 4; mi++) {
                int mb = wm + mi * 16 + grp;
                unsigned a0 = f2tf(As[(kk + thr)     * SPAD + mb]);
                unsigned a1 = f2tf(As[(kk + thr)     * SPAD + mb + 8]);
                unsigned a2 = f2tf(As[(kk + 4 + thr) * SPAD + mb]);
                unsigned a3 = f2tf(As[(kk + 4 + thr) * SPAD + mb + 8]);
                #pragma unroll
                for (int nj = 0; nj < 4; nj++)
                    mma8(acc[mi][nj], a0, a1, a2, a3, bf[nj][0], bf[nj][1]);
            }
        }
        __syncthreads();
        if (kt + 3 < NKT) {
            issue_tile(Ag, ldA, mBase, Bg, ldB, nBase, (kt + 3) * 16, As, Bs, tid);
            CP_COMMIT;
        }
        buf = (buf + 1 == 3) ? 0 : buf + 1;
    }
}

// ---------------- K2: branch GEMM + BN + GELU + fused avg-pool (TF32 MMA) ----------------
__global__ __launch_bounds__(256, 2)
void k_branch_gemm(const float* __restrict__ bbr, const float* __restrict__ bng,
                   const float* __restrict__ bnb) {
    __shared__ float As[3 * TILE_F];
    __shared__ float Bs[3 * TILE_F];

    int mBase = blockIdx.x * 128;
    int b = blockIdx.y, kbr = blockIdx.z;
    const float* Ag = g_E   + ((long)kbr * B_ * C_ + (long)b * C_) * HW_;
    const float* Bg = g_wbT + (long)kbr * C_ * CQ_;

    float acc[4][4][4];
    mma_kloop_pipe(Ag, HW_, mBase, Bg, CQ_, 0, As, Bs, acc);

    int tid = threadIdx.x;
    int lane = tid & 31, w = tid >> 5;
    int wm = (w >> 2) * 64, wn = (w & 3) * 32;
    int grp = lane >> 2, thr = lane & 3;
    const float invbn = rsqrtf(1.0f + 1e-5f);

    #pragma unroll
    for (int nj = 0; nj < 4; nj++) {
        int o  = wn + nj * 8 + thr * 2;
        int og = kbr * CQ_ + o;
        float bi0 = bbr[og],     g0 = bng[og] * invbn,     be0 = bnb[og];
        float bi1 = bbr[og + 1], g1 = bng[og + 1] * invbn, be1 = bnb[og + 1];
        float* out0 = g_ef + ((long)b * C_ + og) * HW_;
        float* out1 = out0 + HW_;
        float s0 = 0.f, s1 = 0.f;
        #pragma unroll
        for (int mi = 0; mi < 4; mi++) {
            int m0 = mBase + wm + mi * 16 + grp;
            float v0 = gelu_exact((acc[mi][nj][0] + bi0) * g0 + be0);
            float v1 = gelu_exact((acc[mi][nj][1] + bi1) * g1 + be1);
            float v2 = gelu_exact((acc[mi][nj][2] + bi0) * g0 + be0);
            float v3 = gelu_exact((acc[mi][nj][3] + bi1) * g1 + be1);
            out0[m0]     = v0;
            out1[m0]     = v1;
            out0[m0 + 8] = v2;
            out1[m0 + 8] = v3;
            s0 += v0 + v2;
            s1 += v1 + v3;
        }
        // reduce 8-pixel partials over the 8 grp lanes (stride 4 in lane id)
        #pragma unroll
        for (int off = 16; off >= 4; off >>= 1) {
            s0 += __shfl_down_sync(0xffffffffu, s0, off);
            s1 += __shfl_down_sync(0xffffffffu, s1, off);
        }
        if (grp == 0) {
            atomicAdd(&g_pooled[b * C_ + og],     s0);
            atomicAdd(&g_pooled[b * C_ + og + 1], s1);
        }
    }
}

// ---------------- K4: squeeze-excite MLP -> att[b][c] ----------------
__global__ void k_se(const float* __restrict__ w1, const float* __restrict__ b1,
                     const float* __restrict__ w2, const float* __restrict__ b2) {
    __shared__ float ps[B_ * C_];
    __shared__ float hs[B_ * CE_];
    int tid = threadIdx.x;  // 256
    for (int i = tid; i < B_ * C_; i += 256) ps[i] = g_pooled[i] * (1.0f / HW_);
    __syncthreads();
    {
        int b = tid >> 6, e = tid & 63;   // 4*64 = 256 threads exactly
        float s = b1[e];
        for (int c = 0; c < C_; c++) s += ps[b * C_ + c] * w1[e * C_ + c];
        hs[b * CE_ + e] = gelu_exact(s);
    }
    __syncthreads();
    for (int i = tid; i < B_ * C_; i += 256) {
        int b = i >> 9, c = i & (C_ - 1);
        float s = b2[c];
        #pragma unroll
        for (int e = 0; e < CE_; e++) s += hs[b * CE_ + e] * w2[c * CE_ + e];
        g_att[i] = 1.0f / (1.0f + expf(-s));
    }
}

// ---------------- K4b: pre-scale fusion weights by att: wfS[b][c][o] ----------------
__global__ void k_scaleB() {
    int i = blockIdx.x * 256 + threadIdx.x;     // 0 .. 4*512*512-1
    int rem = i & (C_ * C_ - 1);
    int b = i >> 18;
    int c = rem >> 9;
    g_wfS[i] = g_att[b * C_ + c] * g_wfT[rem];
}

// ---------------- K5: fusion GEMM (TF32 MMA, pipelined, att pre-folded into B) ----------------
__global__ __launch_bounds__(256, 2)
void k_fuse_gemm(const float* __restrict__ bfuse) {
    __shared__ float As[3 * TILE_F];
    __shared__ float Bs[3 * TILE_F];

    int mBase = blockIdx.x * 128;
    int b = blockIdx.y;
    int nBase = blockIdx.z * 128;
    const float* Ag = g_ef  + (long)b * C_ * HW_;
    const float* Bg = g_wfS + (long)b * C_ * C_;

    float acc[4][4][4];
    mma_kloop_pipe(Ag, HW_, mBase, Bg, C_, nBase, As, Bs, acc);

    int tid = threadIdx.x;
    int lane = tid & 31, w = tid >> 5;
    int wm = (w >> 2) * 64, wn = (w & 3) * 32;
    int grp = lane >> 2, thr = lane & 3;

    #pragma unroll
    for (int nj = 0; nj < 4; nj++) {
        int o = nBase + wn + nj * 8 + thr * 2;
        float bi0 = bfuse[o], bi1 = bfuse[o + 1];
        float* out0 = g_z + ((long)b * C_ + o) * HW_;
        float* out1 = out0 + HW_;
        #pragma unroll
        for (int mi = 0; mi < 4; mi++) {
            int m0 = mBase + wm + mi * 16 + grp;
            out0[m0]     = acc[mi][nj][0] + bi0;
            out1[m0]     = acc[mi][nj][1] + bi1;
            out0[m0 + 8] = acc[mi][nj][2] + bi0;
            out1[m0 + 8] = acc[mi][nj][3] + bi1;
        }
    }
}

// ---------------- K6: per-pixel channel LayerNorm + GELU + residual (float4) ----------------
__global__ void k_ln(const float* __restrict__ x, const float* __restrict__ lng,
                     const float* __restrict__ lnb, float* __restrict__ out) {
    __shared__ float sg[C_], sb[C_];
    for (int i = threadIdx.x; i < C_; i += blockDim.x) { sg[i] = lng[i]; sb[i] = lnb[i]; }
    __syncthreads();

    int t = blockIdx.x * blockDim.x + threadIdx.x;   // 0..P_/4-1
    int b  = t >> 12;                                // 4096 threads per batch
    int pp = (t & 4095) * 4;
    const float4* zp = (const float4*)(g_z + (long)b * C_ * HW_ + pp);
    const float4* xp = (const float4*)(x   + (long)b * C_ * HW_ + pp);
    float4*       op = (float4*)(out + (long)b * C_ * HW_ + pp);
    const int st = HW_ / 4;

    float4 s  = make_float4(0.f, 0.f, 0.f, 0.f);
    float4 ss = make_float4(0.f, 0.f, 0.f, 0.f);
    #pragma unroll 8
    for (int c = 0; c < C_; c++) {
        float4 v = zp[c * st];
        s.x += v.x; s.y += v.y; s.z += v.z; s.w += v.w;
        ss.x += v.x * v.x; ss.y += v.y * v.y; ss.z += v.z * v.z; ss.w += v.w * v.w;
    }
    const float ic = 1.0f / C_;
    float mu0 = s.x * ic, mu1 = s.y * ic, mu2 = s.z * ic, mu3 = s.w * ic;
    float r0 = rsqrtf(fmaxf(ss.x * ic - mu0 * mu0, 0.f) + 1e-6f);
    float r1 = rsqrtf(fmaxf(ss.y * ic - mu1 * mu1, 0.f) + 1e-6f);
    float r2 = rsqrtf(fmaxf(ss.z * ic - mu2 * mu2, 0.f) + 1e-6f);
    float r3 = rsqrtf(fmaxf(ss.w * ic - mu3 * mu3, 0.f) + 1e-6f);

    #pragma unroll 4
    for (int c = 0; c < C_; c++) {
        float4 v = zp[c * st];
        float4 xr = xp[c * st];
        float g = sg[c], be = sb[c];
        float4 o;
        o.x = gelu_exact((v.x - mu0) * r0 * g + be) + xr.x;
        o.y = gelu_exact((v.y - mu1) * r1 * g + be) + xr.y;
        o.z = gelu_exact((v.z - mu2) * r2 * g + be) + xr.z;
        o.w = gelu_exact((v.w - mu3) * r3 * g + be) + xr.w;
        op[c * st] = o;
    }
}

// ---------------- launcher ----------------
extern "C" void kernel_launch(void* const* d_in, const int* in_sizes, int n_in,
                              void* d_out, int out_size) {
    const float* x        = (const float*)d_in[0];
    const float* w_branch = (const float*)d_in[1];
    const float* b_branch = (const float*)d_in[2];
    const float* bn_gamma = (const float*)d_in[3];
    const float* bn_beta  = (const float*)d_in[4];
    const float* w_att1   = (const float*)d_in[5];
    const float* b_att1   = (const float*)d_in[6];
    const float* w_att2   = (const float*)d_in[7];
    const float* b_att2   = (const float*)d_in[8];
    const float* w_fuse   = (const float*)d_in[9];
    const float* b_fuse   = (const float*)d_in[10];
    const float* ln_gamma = (const float*)d_in[11];
    const float* ln_beta  = (const float*)d_in[12];
    float* out = (float*)d_out;

    k_transpose<<<1024, 256>>>(w_branch, w_fuse);
    k_edge<<<B_ * C_, 256>>>(x);
    {
        dim3 g(HW_ / 128, B_, 4);
        k_branch_gemm<<<g, 256>>>(b_branch, bn_gamma, bn_beta);
    }
    k_se<<<1, 256>>>(w_att1, b_att1, w_att2, b_att2);
    k_scaleB<<<(B_ * C_ * C_) / 256, 256>>>();
    {
        dim3 g(HW_ / 128, B_, C_ / 128);
        k_fuse_gemm<<<g, 256>>>(b_fuse);
    }
    k_ln<<<P_ / 512, 128>>>(x, ln_gamma, ln_beta, out);
}

// round 11
// speedup vs baseline: 1.2029x; 1.2029x over previous
#include <cuda_runtime.h>
#include <math.h>

// ---------------- problem constants ----------------
#define B_  4
#define C_  512
#define H_  128
#define W_  128
#define HW_ 16384          // H*W
#define CQ_ 128            // C/4
#define CE_ 64             // C/8
#define P_  65536          // B*H*W

// ---------------- device scratch (no allocs allowed) ----------------
__device__ float g_E[4L * B_ * C_ * HW_];     // 4 edge maps, [k][b][c][hw]
__device__ float g_ef[(long)B_ * C_ * HW_];   // branch features, [b][c][hw]
__device__ float g_z [(long)B_ * C_ * HW_];   // fusion conv out,  [b][c][hw]
__device__ float g_wbT[4 * C_ * CQ_];         // w_branch transposed [k][c][o]
__device__ float g_wfT[C_ * C_];              // w_fuse   transposed [c][o]
__device__ float g_wfS[B_ * C_ * C_];         // att-scaled fuse weights [b][c][o]
__device__ float g_pooled[B_ * C_];           // atomic-accumulated pool sums
__device__ float g_h     [B_ * CE_];          // SE hidden
__device__ float g_att   [B_ * C_];

__device__ __forceinline__ float gelu_exact(float v) {
    return 0.5f * v * (1.0f + erff(v * 0.70710678118654752440f));
}

__device__ __forceinline__ unsigned f2tf(float f) {
    unsigned u;
    asm("cvt.rna.tf32.f32 %0, %1;" : "=r"(u) : "f"(f));
    return u;
}

__device__ __forceinline__ void mma8(float c[4],
                                     unsigned a0, unsigned a1, unsigned a2, unsigned a3,
                                     unsigned b0, unsigned b1) {
    asm volatile(
        "mma.sync.aligned.m16n8k8.row.col.f32.tf32.tf32.f32 "
        "{%0,%1,%2,%3}, {%4,%5,%6,%7}, {%8,%9}, {%0,%1,%2,%3};\n"
        : "+f"(c[0]), "+f"(c[1]), "+f"(c[2]), "+f"(c[3])
        : "r"(a0), "r"(a1), "r"(a2), "r"(a3), "r"(b0), "r"(b1));
}

__device__ __forceinline__ void cp16(void* smem, const void* gmem) {
    unsigned s = (unsigned)__cvta_generic_to_shared(smem);
    asm volatile("cp.async.cg.shared.global [%0], [%1], 16;\n" :: "r"(s), "l"(gmem));
}
#define CP_COMMIT asm volatile("cp.async.commit_group;\n" ::: "memory")
#define CP_WAIT1  asm volatile("cp.async.wait_group 1;\n" ::: "memory")
#define CP_WAIT0  asm volatile("cp.async.wait_group 0;\n" ::: "memory")

// ---------------- K0: weight transposes + zero pooled ----------------
__global__ void k_transpose(const float* __restrict__ wb, const float* __restrict__ wf) {
    int i = blockIdx.x * 256 + threadIdx.x;
    if (i < 4 * C_ * CQ_) {              // wbT[(k*C + c)*CQ + o] = wb[(k*CQ+o)*C + c]
        int o = i & (CQ_ - 1);
        int c = (i >> 7) & (C_ - 1);
        int k = i >> 16;
        g_wbT[i] = wb[(k * CQ_ + o) * C_ + c];
    }
    if (i < C_ * C_) {                   // wfT[c*C + o] = wf[o*C + c]
        int o = i & (C_ - 1);
        int c = i >> 9;
        g_wfT[i] = wf[o * C_ + c];
    }
    if (i < B_ * C_) g_pooled[i] = 0.f;  // reset pool accumulators every launch
}

// ---------------- K1: fixed 3x3 stencils -> 4 edge maps ----------------
__global__ void k_edge(const float* __restrict__ x) {
    int bc = blockIdx.x;                                  // b*C + c
    const float* xp = x + (long)bc * HW_;
    float* e0 = g_E + (long)(0 * B_ * C_ + bc) * HW_;
    float* e1 = g_E + (long)(1 * B_ * C_ + bc) * HW_;
    float* e2 = g_E + (long)(2 * B_ * C_ + bc) * HW_;
    float* e3 = g_E + (long)(3 * B_ * C_ + bc) * HW_;

    for (int p = threadIdx.x; p < HW_; p += blockDim.x) {
        int h = p >> 7, w = p & (W_ - 1);
        int hm = h - 1, hp = h + 1, wm = w - 1, wp = w + 1;
        bool ht = hm >= 0, hb = hp < H_, wl = wm >= 0, wr = wp < W_;
        float v00 = (ht && wl) ? xp[hm * W_ + wm] : 0.f;
        float v01 = (ht)       ? xp[hm * W_ + w ] : 0.f;
        float v02 = (ht && wr) ? xp[hm * W_ + wp] : 0.f;
        float v10 = (wl)       ? xp[h  * W_ + wm] : 0.f;
        float v11 =              xp[h  * W_ + w ];
        float v12 = (wr)       ? xp[h  * W_ + wp] : 0.f;
        float v20 = (hb && wl) ? xp[hp * W_ + wm] : 0.f;
        float v21 = (hb)       ? xp[hp * W_ + w ] : 0.f;
        float v22 = (hb && wr) ? xp[hp * W_ + wp] : 0.f;

        float sh  = (v02 - v00) + 2.f * (v12 - v10) + (v22 - v20);
        float sv  = (v20 - v00) + 2.f * (v21 - v01) + (v22 - v02);
        float lap = v01 + v10 + v12 + v21 - 4.f * v11;
        float d1  = v00 - v02 - v20 + v22;          // K_D2 = -K_D1 => diag = |d1|

        float sobel = sqrtf(sh * sh + sv * sv + 1e-8f);
        float lapA  = fabsf(lap);
        float diag  = fabsf(d1);
        float grad  = sqrtf(sobel * sobel + lapA * lapA + 1e-8f);

        e0[p] = sobel; e1[p] = lapA; e2[p] = diag; e3[p] = grad;
    }
}

// ============== shared TF32 MMA tile core (cp.async double-buffered) ==============
// Block tile 128(M) x 128(N), K-tile 16, 256 threads = 8 warps (2 m x 4 n),
// warp tile 64x32 = 4x4 m16n8k8 atoms. A and B are K-major f32 in gmem.
// Raw f32 staged via cp.async; cvt.rna.tf32 on the fragment-load side.
#define SPAD 132
#define NKT  (C_ / 16)     // 32 k-tiles

__device__ __forceinline__ void issue_tile(
    const float* __restrict__ Ag, long ldA, int mBase,
    const float* __restrict__ Bg, int ldB, int nBase,
    int kc, float* As, float* Bs, int tid)
{
    #pragma unroll
    for (int i = 0; i < 2; i++) {
        int idx = tid + i * 256;          // 0..511
        int row = idx >> 5;               // 0..15
        int c4  = (idx & 31) * 4;         // 0..124
        cp16(&As[row * SPAD + c4], &Ag[(long)(kc + row) * ldA + mBase + c4]);
        cp16(&Bs[row * SPAD + c4], &Bg[(long)(kc + row) * ldB + nBase + c4]);
    }
}

__device__ __forceinline__ void mma_kloop_pipe(
    const float* __restrict__ Ag, long ldA, int mBase,
    const float* __restrict__ Bg, int ldB, int nBase,
    float* AsBuf, float* BsBuf,           // each 2 * 16*SPAD floats
    float acc[4][4][4])
{
    int tid = threadIdx.x;
    int lane = tid & 31, w = tid >> 5;
    int wm = (w >> 2) * 64, wn = (w & 3) * 32;
    int grp = lane >> 2, thr = lane & 3;

    #pragma unroll
    for (int mi = 0; mi < 4; mi++)
        #pragma unroll
        for (int nj = 0; nj < 4; nj++)
            #pragma unroll
            for (int r = 0; r < 4; r++) acc[mi][nj][r] = 0.f;

    float* As0 = AsBuf;            float* As1 = AsBuf + 16 * SPAD;
    float* Bs0 = BsBuf;            float* Bs1 = BsBuf + 16 * SPAD;

    issue_tile(Ag, ldA, mBase, Bg, ldB, nBase, 0,  As0, Bs0, tid); CP_COMMIT;
    issue_tile(Ag, ldA, mBase, Bg, ldB, nBase, 16, As1, Bs1, tid); CP_COMMIT;

    for (int kt = 0; kt < NKT; kt++) {
        if (kt == NKT - 1) { CP_WAIT0; } else { CP_WAIT1; }
        __syncthreads();

        float* As = (kt & 1) ? As1 : As0;
        float* Bs = (kt & 1) ? Bs1 : Bs0;

        #pragma unroll
        for (int kk = 0; kk < 16; kk += 8) {
            unsigned bf[4][2];
            #pragma unroll
            for (int nj = 0; nj < 4; nj++) {
                bf[nj][0] = f2tf(Bs[(kk + thr)     * SPAD + wn + nj * 8 + grp]);
                bf[nj][1] = f2tf(Bs[(kk + 4 + thr) * SPAD + wn + nj * 8 + grp]);
            }
            #pragma unroll
            for (int mi = 0; mi < 4; mi++) {
                int mb = wm + mi * 16 + grp;
                unsigned a0 = f2tf(As[(kk + thr)     * SPAD + mb]);
                unsigned a1 = f2tf(As[(kk + thr)     * SPAD + mb + 8]);
                unsigned a2 = f2tf(As[(kk + 4 + thr) * SPAD + mb]);
                unsigned a3 = f2tf(As[(kk + 4 + thr) * SPAD + mb + 8]);
                #pragma unroll
                for (int nj = 0; nj < 4; nj++)
                    mma8(acc[mi][nj], a0, a1, a2, a3, bf[nj][0], bf[nj][1]);
            }
        }
        __syncthreads();
        if (kt + 2 < NKT) {
            issue_tile(Ag, ldA, mBase, Bg, ldB, nBase, (kt + 2) * 16, As, Bs, tid);
            CP_COMMIT;
        }
    }
}

// ---------------- K2: branch GEMM + BN + GELU + fused avg-pool (TF32 MMA) ----------------
__global__ __launch_bounds__(256, 2)
void k_branch_gemm(const float* __restrict__ bbr, const float* __restrict__ bng,
                   const float* __restrict__ bnb) {
    __shared__ float As[2 * 16 * SPAD];
    __shared__ float Bs[2 * 16 * SPAD];

    int mBase = blockIdx.x * 128;
    int b = blockIdx.y, kbr = blockIdx.z;
    const float* Ag = g_E   + ((long)kbr * B_ * C_ + (long)b * C_) * HW_;
    const float* Bg = g_wbT + (long)kbr * C_ * CQ_;

    float acc[4][4][4];
    mma_kloop_pipe(Ag, HW_, mBase, Bg, CQ_, 0, As, Bs, acc);

    int tid = threadIdx.x;
    int lane = tid & 31, w = tid >> 5;
    int wm = (w >> 2) * 64, wn = (w & 3) * 32;
    int grp = lane >> 2, thr = lane & 3;
    const float invbn = rsqrtf(1.0f + 1e-5f);

    #pragma unroll
    for (int nj = 0; nj < 4; nj++) {
        int o  = wn + nj * 8 + thr * 2;
        int og = kbr * CQ_ + o;
        float bi0 = bbr[og],     g0 = bng[og] * invbn,     be0 = bnb[og];
        float bi1 = bbr[og + 1], g1 = bng[og + 1] * invbn, be1 = bnb[og + 1];
        float* out0 = g_ef + ((long)b * C_ + og) * HW_;
        float* out1 = out0 + HW_;
        float s0 = 0.f, s1 = 0.f;
        #pragma unroll
        for (int mi = 0; mi < 4; mi++) {
            int m0 = mBase + wm + mi * 16 + grp;
            float v0 = gelu_exact((acc[mi][nj][0] + bi0) * g0 + be0);
            float v1 = gelu_exact((acc[mi][nj][1] + bi1) * g1 + be1);
            float v2 = gelu_exact((acc[mi][nj][2] + bi0) * g0 + be0);
            float v3 = gelu_exact((acc[mi][nj][3] + bi1) * g1 + be1);
            out0[m0]     = v0;
            out1[m0]     = v1;
            out0[m0 + 8] = v2;
            out1[m0 + 8] = v3;
            s0 += v0 + v2;
            s1 += v1 + v3;
        }
        // reduce 8-pixel partials over the 8 grp lanes (stride 4 in lane id)
        #pragma unroll
        for (int off = 16; off >= 4; off >>= 1) {
            s0 += __shfl_down_sync(0xffffffffu, s0, off);
            s1 += __shfl_down_sync(0xffffffffu, s1, off);
        }
        if (grp == 0) {
            atomicAdd(&g_pooled[b * C_ + og],     s0);
            atomicAdd(&g_pooled[b * C_ + og + 1], s1);
        }
    }
}

// ---------------- K4a: SE layer 1 — one warp per hidden unit ----------------
// grid 32 x 256: 256 warps total, warp id = b*CE + e
__global__ void k_se1(const float* __restrict__ w1, const float* __restrict__ b1) {
    int gw = (blockIdx.x * 256 + threadIdx.x) >> 5;   // 0..255
    int lane = threadIdx.x & 31;
    int b = gw >> 6, e = gw & (CE_ - 1);
    const float* wr = w1 + e * C_;
    const float* pr = g_pooled + b * C_;
    float s = 0.f;
    #pragma unroll
    for (int c = lane; c < C_; c += 32)
        s += pr[c] * wr[c];
    #pragma unroll
    for (int off = 16; off > 0; off >>= 1)
        s += __shfl_down_sync(0xffffffffu, s, off);
    if (lane == 0)
        g_h[gw] = gelu_exact(s * (1.0f / HW_) + b1[e]);
}

// ---------------- K4b: SE layer 2 — h in smem, one thread per att output ----------------
// grid 8 x 256: thread i -> att[b][c], i = b*C + c
__global__ void k_se2(const float* __restrict__ w2, const float* __restrict__ b2) {
    __shared__ float hs[B_ * CE_];
    int tid = threadIdx.x;
    if (tid < B_ * CE_) hs[tid] = g_h[tid];
    __syncthreads();
    int i = blockIdx.x * 256 + tid;       // 0..2047
    int b = i >> 9, c = i & (C_ - 1);
    const float* wr = w2 + c * CE_;
    float s = b2[c];
    #pragma unroll
    for (int e = 0; e < CE_; e++) s += hs[b * CE_ + e] * wr[e];
    g_att[i] = 1.0f / (1.0f + expf(-s));
}

// ---------------- K4c: pre-scale fusion weights by att: wfS[b][c][o] ----------------
__global__ void k_scaleB() {
    int i = blockIdx.x * 256 + threadIdx.x;     // 0 .. 4*512*512-1
    int rem = i & (C_ * C_ - 1);
    int b = i >> 18;
    int c = rem >> 9;
    g_wfS[i] = g_att[b * C_ + c] * g_wfT[rem];
}

// ---------------- K5: fusion GEMM (TF32 MMA, pipelined, att pre-folded into B) ----------------
__global__ __launch_bounds__(256, 2)
void k_fuse_gemm(const float* __restrict__ bfuse) {
    __shared__ float As[2 * 16 * SPAD];
    __shared__ float Bs[2 * 16 * SPAD];

    int mBase = blockIdx.x * 128;
    int b = blockIdx.y;
    int nBase = blockIdx.z * 128;
    const float* Ag = g_ef  + (long)b * C_ * HW_;
    const float* Bg = g_wfS + (long)b * C_ * C_;

    float acc[4][4][4];
    mma_kloop_pipe(Ag, HW_, mBase, Bg, C_, nBase, As, Bs, acc);

    int tid = threadIdx.x;
    int lane = tid & 31, w = tid >> 5;
    int wm = (w >> 2) * 64, wn = (w & 3) * 32;
    int grp = lane >> 2, thr = lane & 3;

    #pragma unroll
    for (int nj = 0; nj < 4; nj++) {
        int o = nBase + wn + nj * 8 + thr * 2;
        float bi0 = bfuse[o], bi1 = bfuse[o + 1];
        float* out0 = g_z + ((long)b * C_ + o) * HW_;
        float* out1 = out0 + HW_;
        #pragma unroll
        for (int mi = 0; mi < 4; mi++) {
            int m0 = mBase + wm + mi * 16 + grp;
            out0[m0]     = acc[mi][nj][0] + bi0;
            out1[m0]     = acc[mi][nj][1] + bi1;
            out0[m0 + 8] = acc[mi][nj][2] + bi0;
            out1[m0 + 8] = acc[mi][nj][3] + bi1;
        }
    }
}

// ---------------- K6: per-pixel channel LayerNorm + GELU + residual ----------------
__global__ void k_ln(const float* __restrict__ x, const float* __restrict__ lng,
                     const float* __restrict__ lnb, float* __restrict__ out) {
    int p = blockIdx.x * blockDim.x + threadIdx.x;   // 0..P-1
    if (p >= P_) return;
    int b  = p >> 14;
    int pp = p & (HW_ - 1);
    const float* zp = g_z + (long)b * C_ * HW_ + pp;
    const float* xp = x   + (long)b * C_ * HW_ + pp;
    float*       op = out + (long)b * C_ * HW_ + pp;

    float s = 0.f, ss = 0.f;
    #pragma unroll 8
    for (int c = 0; c < C_; c++) {
        float v = zp[(long)c * HW_];
        s += v; ss += v * v;
    }
    float mu  = s * (1.0f / C_);
    float var = ss * (1.0f / C_) - mu * mu;
    var = fmaxf(var, 0.f);
    float rstd = rsqrtf(var + 1e-6f);

    #pragma unroll 8
    for (int c = 0; c < C_; c++) {
        float v = zp[(long)c * HW_];
        float t = (v - mu) * rstd * lng[c] + lnb[c];
        op[(long)c * HW_] = gelu_exact(t) + xp[(long)c * HW_];
    }
}

// ---------------- launcher ----------------
extern "C" void kernel_launch(void* const* d_in, const int* in_sizes, int n_in,
                              void* d_out, int out_size) {
    const float* x        = (const float*)d_in[0];
    const float* w_branch = (const float*)d_in[1];
    const float* b_branch = (const float*)d_in[2];
    const float* bn_gamma = (const float*)d_in[3];
    const float* bn_beta  = (const float*)d_in[4];
    const float* w_att1   = (const float*)d_in[5];
    const float* b_att1   = (const float*)d_in[6];
    const float* w_att2   = (const float*)d_in[7];
    const float* b_att2   = (const float*)d_in[8];
    const float* w_fuse   = (const float*)d_in[9];
    const float* b_fuse   = (const float*)d_in[10];
    const float* ln_gamma = (const float*)d_in[11];
    const float* ln_beta  = (const float*)d_in[12];
    float* out = (float*)d_out;

    k_transpose<<<1024, 256>>>(w_branch, w_fuse);
    k_edge<<<B_ * C_, 256>>>(x);
    {
        dim3 g(HW_ / 128, B_, 4);
        k_branch_gemm<<<g, 256>>>(b_branch, bn_gamma, bn_beta);
    }
    k_se1<<<32, 256>>>(w_att1, b_att1);
    k_se2<<<8, 256>>>(w_att2, b_att2);
    k_scaleB<<<(B_ * C_ * C_) / 256, 256>>>();
    {
        dim3 g(HW_ / 128, B_, C_ / 128);
        k_fuse_gemm<<<g, 256>>>(b_fuse);
    }
    k_ln<<<P_ / 128, 128>>>(x, ln_gamma, ln_beta, out);
}

// round 12
// speedup vs baseline: 1.3149x; 1.0931x over previous
#include <cuda_runtime.h>
#include <math.h>

// ---------------- problem constants ----------------
#define B_  4
#define C_  512
#define H_  128
#define W_  128
#define HW_ 16384          // H*W
#define CQ_ 128            // C/4
#define CE_ 64             // C/8
#define P_  65536          // B*H*W

// ---------------- device scratch (no allocs allowed) ----------------
__device__ float g_E[4L * B_ * C_ * HW_];     // 4 edge maps, [k][b][c][hw]
__device__ float g_ef[(long)B_ * C_ * HW_];   // branch features, [b][c][hw]
__device__ float g_z [(long)B_ * C_ * HW_];   // fusion conv out,  [b][c][hw]
__device__ float g_wbT[4 * C_ * CQ_];         // w_branch transposed [k][c][o]
__device__ float g_wfT[C_ * C_];              // w_fuse   transposed [c][o]
__device__ float g_wfS[B_ * C_ * C_];         // att-scaled fuse weights [b][c][o]
__device__ float g_pooled[B_ * C_];           // atomic-accumulated pool sums
__device__ float g_h     [B_ * CE_];          // SE hidden
__device__ float g_att   [B_ * C_];
__device__ float g_lnsum[P_];                 // per-pixel sum of z over channels
__device__ float g_lnssq[P_];                 // per-pixel sum of z^2

__device__ __forceinline__ float gelu_exact(float v) {
    return 0.5f * v * (1.0f + erff(v * 0.70710678118654752440f));
}

__device__ __forceinline__ unsigned f2tf(float f) {
    unsigned u;
    asm("cvt.rna.tf32.f32 %0, %1;" : "=r"(u) : "f"(f));
    return u;
}

__device__ __forceinline__ void mma8(float c[4],
                                     unsigned a0, unsigned a1, unsigned a2, unsigned a3,
                                     unsigned b0, unsigned b1) {
    asm volatile(
        "mma.sync.aligned.m16n8k8.row.col.f32.tf32.tf32.f32 "
        "{%0,%1,%2,%3}, {%4,%5,%6,%7}, {%8,%9}, {%0,%1,%2,%3};\n"
        : "+f"(c[0]), "+f"(c[1]), "+f"(c[2]), "+f"(c[3])
        : "r"(a0), "r"(a1), "r"(a2), "r"(a3), "r"(b0), "r"(b1));
}

__device__ __forceinline__ void cp16(void* smem, const void* gmem) {
    unsigned s = (unsigned)__cvta_generic_to_shared(smem);
    asm volatile("cp.async.cg.shared.global [%0], [%1], 16;\n" :: "r"(s), "l"(gmem));
}
#define CP_COMMIT asm volatile("cp.async.commit_group;\n" ::: "memory")
#define CP_WAIT1  asm volatile("cp.async.wait_group 1;\n" ::: "memory")
#define CP_WAIT0  asm volatile("cp.async.wait_group 0;\n" ::: "memory")

// ---------------- K0: weight transposes + zero accumulators ----------------
__global__ void k_transpose(const float* __restrict__ wb, const float* __restrict__ wf) {
    int i = blockIdx.x * 256 + threadIdx.x;    // 0..262143
    if (i < 4 * C_ * CQ_) {              // wbT[(k*C + c)*CQ + o] = wb[(k*CQ+o)*C + c]
        int o = i & (CQ_ - 1);
        int c = (i >> 7) & (C_ - 1);
        int k = i >> 16;
        g_wbT[i] = wb[(k * CQ_ + o) * C_ + c];
    }
    if (i < C_ * C_) {                   // wfT[c*C + o] = wf[o*C + c]
        int o = i & (C_ - 1);
        int c = i >> 9;
        g_wfT[i] = wf[o * C_ + c];
    }
    if (i < B_ * C_) g_pooled[i] = 0.f;  // reset pool accumulators every launch
    if (i < P_) { g_lnsum[i] = 0.f; g_lnssq[i] = 0.f; }
}

// ---------------- K1: fixed 3x3 stencils -> 4 edge maps (float4, 4 px/thread) ----------------
__global__ void k_edge(const float* __restrict__ x) {
    int bc = blockIdx.x;                                  // b*C + c
    const float* xp = x + (long)bc * HW_;
    float4* e0 = (float4*)(g_E + (long)(0 * B_ * C_ + bc) * HW_);
    float4* e1 = (float4*)(g_E + (long)(1 * B_ * C_ + bc) * HW_);
    float4* e2 = (float4*)(g_E + (long)(2 * B_ * C_ + bc) * HW_);
    float4* e3 = (float4*)(g_E + (long)(3 * B_ * C_ + bc) * HW_);

    const float4 z4 = make_float4(0.f, 0.f, 0.f, 0.f);
    for (int q = threadIdx.x; q < HW_ / 4; q += blockDim.x) {
        int h  = q >> 5;                 // 32 quads per row
        int w4 = (q & 31) << 2;
        bool ht = h > 0, hb = h < H_ - 1;
        bool wl = w4 > 0, wr = w4 + 4 < W_;
        const float* rm = xp + (h - 1) * W_;
        const float* rc = xp + h * W_;
        const float* rp = xp + (h + 1) * W_;

        float4 cm = ht ? *(const float4*)(rm + w4) : z4;
        float4 cc =      *(const float4*)(rc + w4);
        float4 cp = hb ? *(const float4*)(rp + w4) : z4;
        float am[6] = { (ht && wl) ? rm[w4 - 1] : 0.f, cm.x, cm.y, cm.z, cm.w,
                        (ht && wr) ? rm[w4 + 4] : 0.f };
        float ac[6] = { (wl)       ? rc[w4 - 1] : 0.f, cc.x, cc.y, cc.z, cc.w,
                        (wr)       ? rc[w4 + 4] : 0.f };
        float ap[6] = { (hb && wl) ? rp[w4 - 1] : 0.f, cp.x, cp.y, cp.z, cp.w,
                        (hb && wr) ? rp[w4 + 4] : 0.f };

        float4 o0, o1, o2, o3;
        #pragma unroll
        for (int j = 0; j < 4; j++) {
            float v00 = am[j], v01 = am[j + 1], v02 = am[j + 2];
            float v10 = ac[j], v11 = ac[j + 1], v12 = ac[j + 2];
            float v20 = ap[j], v21 = ap[j + 1], v22 = ap[j + 2];

            float sh  = (v02 - v00) + 2.f * (v12 - v10) + (v22 - v20);
            float sv  = (v20 - v00) + 2.f * (v21 - v01) + (v22 - v02);
            float lap = v01 + v10 + v12 + v21 - 4.f * v11;
            float d1  = v00 - v02 - v20 + v22;      // K_D2 = -K_D1 => diag = |d1|

            float sobel = sqrtf(sh * sh + sv * sv + 1e-8f);
            float lapA  = fabsf(lap);
            float diag  = fabsf(d1);
            float grad  = sqrtf(sobel * sobel + lapA * lapA + 1e-8f);

            ((float*)&o0)[j] = sobel;
            ((float*)&o1)[j] = lapA;
            ((float*)&o2)[j] = diag;
            ((float*)&o3)[j] = grad;
        }
        e0[q] = o0; e1[q] = o1; e2[q] = o2; e3[q] = o3;
    }
}

// ============== shared TF32 MMA tile core (cp.async double-buffered) ==============
#define SPAD 132
#define NKT  (C_ / 16)     // 32 k-tiles

__device__ __forceinline__ void issue_tile(
    const float* __restrict__ Ag, long ldA, int mBase,
    const float* __restrict__ Bg, int ldB, int nBase,
    int kc, float* As, float* Bs, int tid)
{
    #pragma unroll
    for (int i = 0; i < 2; i++) {
        int idx = tid + i * 256;          // 0..511
        int row = idx >> 5;               // 0..15
        int c4  = (idx & 31) * 4;         // 0..124
        cp16(&As[row * SPAD + c4], &Ag[(long)(kc + row) * ldA + mBase + c4]);
        cp16(&Bs[row * SPAD + c4], &Bg[(long)(kc + row) * ldB + nBase + c4]);
    }
}

__device__ __forceinline__ void mma_kloop_pipe(
    const float* __restrict__ Ag, long ldA, int mBase,
    const float* __restrict__ Bg, int ldB, int nBase,
    float* AsBuf, float* BsBuf,           // each 2 * 16*SPAD floats
    float acc[4][4][4])
{
    int tid = threadIdx.x;
    int lane = tid & 31, w = tid >> 5;
    int wm = (w >> 2) * 64, wn = (w & 3) * 32;
    int grp = lane >> 2, thr = lane & 3;

    #pragma unroll
    for (int mi = 0; mi < 4; mi++)
        #pragma unroll
        for (int nj = 0; nj < 4; nj++)
            #pragma unroll
            for (int r = 0; r < 4; r++) acc[mi][nj][r] = 0.f;

    float* As0 = AsBuf;            float* As1 = AsBuf + 16 * SPAD;
    float* Bs0 = BsBuf;            float* Bs1 = BsBuf + 16 * SPAD;

    issue_tile(Ag, ldA, mBase, Bg, ldB, nBase, 0,  As0, Bs0, tid); CP_COMMIT;
    issue_tile(Ag, ldA, mBase, Bg, ldB, nBase, 16, As1, Bs1, tid); CP_COMMIT;

    for (int kt = 0; kt < NKT; kt++) {
        if (kt == NKT - 1) { CP_WAIT0; } else { CP_WAIT1; }
        __syncthreads();

        float* As = (kt & 1) ? As1 : As0;
        float* Bs = (kt & 1) ? Bs1 : Bs0;

        #pragma unroll
        for (int kk = 0; kk < 16; kk += 8) {
            unsigned bf[4][2];
            #pragma unroll
            for (int nj = 0; nj < 4; nj++) {
                bf[nj][0] = f2tf(Bs[(kk + thr)     * SPAD + wn + nj * 8 + grp]);
                bf[nj][1] = f2tf(Bs[(kk + 4 + thr) * SPAD + wn + nj * 8 + grp]);
            }
            #pragma unroll
            for (int mi = 0; mi < 4; mi++) {
                int mb = wm + mi * 16 + grp;
                unsigned a0 = f2tf(As[(kk + thr)     * SPAD + mb]);
                unsigned a1 = f2tf(As[(kk + thr)     * SPAD + mb + 8]);
                unsigned a2 = f2tf(As[(kk + 4 + thr) * SPAD + mb]);
                unsigned a3 = f2tf(As[(kk + 4 + thr) * SPAD + mb + 8]);
                #pragma unroll
                for (int nj = 0; nj < 4; nj++)
                    mma8(acc[mi][nj], a0, a1, a2, a3, bf[nj][0], bf[nj][1]);
            }
        }
        __syncthreads();
        if (kt + 2 < NKT) {
            issue_tile(Ag, ldA, mBase, Bg, ldB, nBase, (kt + 2) * 16, As, Bs, tid);
            CP_COMMIT;
        }
    }
}

// ---------------- K2: branch GEMM + BN + GELU + fused avg-pool (TF32 MMA) ----------------
__global__ __launch_bounds__(256, 2)
void k_branch_gemm(const float* __restrict__ bbr, const float* __restrict__ bng,
                   const float* __restrict__ bnb) {
    __shared__ float As[2 * 16 * SPAD];
    __shared__ float Bs[2 * 16 * SPAD];

    int mBase = blockIdx.x * 128;
    int b = blockIdx.y, kbr = blockIdx.z;
    const float* Ag = g_E   + ((long)kbr * B_ * C_ + (long)b * C_) * HW_;
    const float* Bg = g_wbT + (long)kbr * C_ * CQ_;

    float acc[4][4][4];
    mma_kloop_pipe(Ag, HW_, mBase, Bg, CQ_, 0, As, Bs, acc);

    int tid = threadIdx.x;
    int lane = tid & 31, w = tid >> 5;
    int wm = (w >> 2) * 64, wn = (w & 3) * 32;
    int grp = lane >> 2, thr = lane & 3;
    const float invbn = rsqrtf(1.0f + 1e-5f);

    #pragma unroll
    for (int nj = 0; nj < 4; nj++) {
        int o  = wn + nj * 8 + thr * 2;
        int og = kbr * CQ_ + o;
        float bi0 = bbr[og],     g0 = bng[og] * invbn,     be0 = bnb[og];
        float bi1 = bbr[og + 1], g1 = bng[og + 1] * invbn, be1 = bnb[og + 1];
        float* out0 = g_ef + ((long)b * C_ + og) * HW_;
        float* out1 = out0 + HW_;
        float s0 = 0.f, s1 = 0.f;
        #pragma unroll
        for (int mi = 0; mi < 4; mi++) {
            int m0 = mBase + wm + mi * 16 + grp;
            float v0 = gelu_exact((acc[mi][nj][0] + bi0) * g0 + be0);
            float v1 = gelu_exact((acc[mi][nj][1] + bi1) * g1 + be1);
            float v2 = gelu_exact((acc[mi][nj][2] + bi0) * g0 + be0);
            float v3 = gelu_exact((acc[mi][nj][3] + bi1) * g1 + be1);
            out0[m0]     = v0;
            out1[m0]     = v1;
            out0[m0 + 8] = v2;
            out1[m0 + 8] = v3;
            s0 += v0 + v2;
            s1 += v1 + v3;
        }
        #pragma unroll
        for (int off = 16; off >= 4; off >>= 1) {
            s0 += __shfl_down_sync(0xffffffffu, s0, off);
            s1 += __shfl_down_sync(0xffffffffu, s1, off);
        }
        if (grp == 0) {
            atomicAdd(&g_pooled[b * C_ + og],     s0);
            atomicAdd(&g_pooled[b * C_ + og + 1], s1);
        }
    }
}

// ---------------- K4a: SE layer 1 — one warp per hidden unit ----------------
__global__ void k_se1(const float* __restrict__ w1, const float* __restrict__ b1) {
    int gw = (blockIdx.x * 256 + threadIdx.x) >> 5;   // 0..255
    int lane = threadIdx.x & 31;
    int b = gw >> 6, e = gw & (CE_ - 1);
    const float* wr = w1 + e * C_;
    const float* pr = g_pooled + b * C_;
    float s = 0.f;
    #pragma unroll
    for (int c = lane; c < C_; c += 32)
        s += pr[c] * wr[c];
    #pragma unroll
    for (int off = 16; off > 0; off >>= 1)
        s += __shfl_down_sync(0xffffffffu, s, off);
    if (lane == 0)
        g_h[gw] = gelu_exact(s * (1.0f / HW_) + b1[e]);
}

// ---------------- K4b: SE layer 2 — h in smem, one thread per att output ----------------
__global__ void k_se2(const float* __restrict__ w2, const float* __restrict__ b2) {
    __shared__ float hs[B_ * CE_];
    int tid = threadIdx.x;
    if (tid < B_ * CE_) hs[tid] = g_h[tid];
    __syncthreads();
    int i = blockIdx.x * 256 + tid;       // 0..2047
    int b = i >> 9, c = i & (C_ - 1);
    const float* wr = w2 + c * CE_;
    float s = b2[c];
    #pragma unroll
    for (int e = 0; e < CE_; e++) s += hs[b * CE_ + e] * wr[e];
    g_att[i] = 1.0f / (1.0f + expf(-s));
}

// ---------------- K4c: pre-scale fusion weights by att: wfS[b][c][o] ----------------
__global__ void k_scaleB() {
    int i = blockIdx.x * 256 + threadIdx.x;     // 0 .. 4*512*512-1
    int rem = i & (C_ * C_ - 1);
    int b = i >> 18;
    int c = rem >> 9;
    g_wfS[i] = g_att[b * C_ + c] * g_wfT[rem];
}

// ---------------- K5: fusion GEMM + LN-stats accumulation ----------------
__global__ __launch_bounds__(256, 2)
void k_fuse_gemm(const float* __restrict__ bfuse) {
    __shared__ float As[2 * 16 * SPAD];
    __shared__ float Bs[2 * 16 * SPAD];
    __shared__ float s_sum[128];
    __shared__ float s_ssq[128];

    int mBase = blockIdx.x * 128;
    int b = blockIdx.y;
    int nBase = blockIdx.z * 128;
    const float* Ag = g_ef  + (long)b * C_ * HW_;
    const float* Bg = g_wfS + (long)b * C_ * C_;

    int tid = threadIdx.x;
    if (tid < 128) { s_sum[tid] = 0.f; s_ssq[tid] = 0.f; }

    float acc[4][4][4];
    mma_kloop_pipe(Ag, HW_, mBase, Bg, C_, nBase, As, Bs, acc);

    int lane = tid & 31, w = tid >> 5;
    int wm = (w >> 2) * 64, wn = (w & 3) * 32;
    int grp = lane >> 2, thr = lane & 3;

    float bi[4][2];
    #pragma unroll
    for (int nj = 0; nj < 4; nj++) {
        int o = nBase + wn + nj * 8 + thr * 2;
        bi[nj][0] = bfuse[o];
        bi[nj][1] = bfuse[o + 1];
    }

    #pragma unroll
    for (int mi = 0; mi < 4; mi++) {
        int m0 = wm + mi * 16 + grp;        // local pixel 0..127 (and m0+8)
        float sa = 0.f, qa = 0.f, sb = 0.f, qb = 0.f;
        #pragma unroll
        for (int nj = 0; nj < 4; nj++) {
            int o = nBase + wn + nj * 8 + thr * 2;
            float v0 = acc[mi][nj][0] + bi[nj][0];
            float v1 = acc[mi][nj][1] + bi[nj][1];
            float v2 = acc[mi][nj][2] + bi[nj][0];
            float v3 = acc[mi][nj][3] + bi[nj][1];
            float* out0 = g_z + ((long)b * C_ + o) * HW_ + mBase;
            out0[m0]           = v0;
            out0[HW_ + m0]     = v1;
            out0[m0 + 8]       = v2;
            out0[HW_ + m0 + 8] = v3;
            sa += v0 + v1; qa += v0 * v0 + v1 * v1;
            sb += v2 + v3; qb += v2 * v2 + v3 * v3;
        }
        atomicAdd(&s_sum[m0], sa);     atomicAdd(&s_ssq[m0], qa);
        atomicAdd(&s_sum[m0 + 8], sb); atomicAdd(&s_ssq[m0 + 8], qb);
    }
    __syncthreads();
    if (tid < 128) {
        long p = (long)b * HW_ + mBase + tid;
        atomicAdd(&g_lnsum[p], s_sum[tid]);
        atomicAdd(&g_lnssq[p], s_ssq[tid]);
    }
}

// ---------------- K6: one-pass LayerNorm + GELU + residual (stats precomputed) ----------------
__global__ void k_ln(const float* __restrict__ x, const float* __restrict__ lng,
                     const float* __restrict__ lnb, float* __restrict__ out) {
    int p = blockIdx.x * blockDim.x + threadIdx.x;   // 0..P-1
    if (p >= P_) return;
    int b  = p >> 14;
    int pp = p & (HW_ - 1);
    const float* zp = g_z + (long)b * C_ * HW_ + pp;
    const float* xp = x   + (long)b * C_ * HW_ + pp;
    float*       op = out + (long)b * C_ * HW_ + pp;

    const float ic = 1.0f / C_;
    float mu  = g_lnsum[p] * ic;
    float var = g_lnssq[p] * ic - mu * mu;
    var = fmaxf(var, 0.f);
    float rstd = rsqrtf(var + 1e-6f);

    #pragma unroll 8
    for (int c = 0; c < C_; c++) {
        float v = zp[(long)c * HW_];
        float t = (v - mu) * rstd * lng[c] + lnb[c];
        op[(long)c * HW_] = gelu_exact(t) + xp[(long)c * HW_];
    }
}

// ---------------- launcher ----------------
extern "C" void kernel_launch(void* const* d_in, const int* in_sizes, int n_in,
                              void* d_out, int out_size) {
    const float* x        = (const float*)d_in[0];
    const float* w_branch = (const float*)d_in[1];
    const float* b_branch = (const float*)d_in[2];
    const float* bn_gamma = (const float*)d_in[3];
    const float* bn_beta  = (const float*)d_in[4];
    const float* w_att1   = (const float*)d_in[5];
    const float* b_att1   = (const float*)d_in[6];
    const float* w_att2   = (const float*)d_in[7];
    const float* b_att2   = (const float*)d_in[8];
    const float* w_fuse   = (const float*)d_in[9];
    const float* b_fuse   = (const float*)d_in[10];
    const float* ln_gamma = (const float*)d_in[11];
    const float* ln_beta  = (const float*)d_in[12];
    float* out = (float*)d_out;

    k_transpose<<<1024, 256>>>(w_branch, w_fuse);
    k_edge<<<B_ * C_, 256>>>(x);
    {
        dim3 g(HW_ / 128, B_, 4);
        k_branch_gemm<<<g, 256>>>(b_branch, bn_gamma, bn_beta);
    }
    k_se1<<<32, 256>>>(w_att1, b_att1);
    k_se2<<<8, 256>>>(w_att2, b_att2);
    k_scaleB<<<(B_ * C_ * C_) / 256, 256>>>();
    {
        dim3 g(HW_ / 128, B_, C_ / 128);
        k_fuse_gemm<<<g, 256>>>(b_fuse);
    }
    k_ln<<<P_ / 128, 128>>>(x, ln_gamma, ln_beta, out);
}